// round 1
// baseline (speedup 1.0000x reference)
#include <cuda_runtime.h>
#include <math.h>

#define B_    32
#define T_    256
#define D_    512
#define NVEC  8192   // B_*T_
#define KCODE 8192

// ---- scratch (device globals; no allocations allowed) ----
__device__ unsigned long long g_best[NVEC];   // packed (ordered_score<<32)|idx
__device__ float g_cnorm[KCODE];
__device__ float g_znorm[NVEC];
__device__ int   g_counts[KCODE];
__device__ int   g_idx[NVEC];
__device__ float g_loss;

// ---- ordered-float helpers (monotonic float<->uint map) ----
__device__ __forceinline__ unsigned int ford(float f) {
    unsigned int u = __float_as_uint(f);
    return u ^ ((u >> 31) ? 0xFFFFFFFFu : 0x80000000u);
}
__device__ __forceinline__ float funord(unsigned int u) {
    u ^= ((u >> 31) ? 0x80000000u : 0xFFFFFFFFu);
    return __uint_as_float(u);
}

// ---- reset state every launch (graph replays must be deterministic) ----
__global__ void k_init() {
    int i = blockIdx.x * 256 + threadIdx.x;
    if (i < NVEC)  g_best[i]   = 0xFFFFFFFFFFFFFFFFull;
    if (i < KCODE) g_counts[i] = 0;
    if (i == 0)    g_loss = 0.f;
}

// ---- ||c_k||^2 : one warp per code, coalesced ----
__global__ void k_cnorm(const float* __restrict__ cb) {
    int warp = (blockIdx.x * blockDim.x + threadIdx.x) >> 5;
    int lane = threadIdx.x & 31;
    if (warp >= KCODE) return;
    const float* row = cb + (size_t)warp * D_;
    float s = 0.f;
    #pragma unroll
    for (int e = lane; e < D_; e += 32) { float v = row[e]; s += v * v; }
    #pragma unroll
    for (int o = 16; o; o >>= 1) s += __shfl_xor_sync(0xFFFFFFFFu, s, o);
    if (!lane) g_cnorm[warp] = s;
}

// ---- ||z_n||^2 : thread per (b,t), coalesced along t ----
__global__ void k_znorm(const float* __restrict__ z) {
    int n = blockIdx.x * 256 + threadIdx.x;
    if (n >= NVEC) return;
    int b = n >> 8, t = n & 255;
    const float* base = z + (size_t)b * D_ * T_ + t;
    float s = 0.f;
    #pragma unroll 8
    for (int d = 0; d < D_; d++) { float v = base[d * T_]; s += v * v; }
    g_znorm[n] = s;
}

// ---- fused fp32 SGEMM (score = cnorm - 2*z.c) + per-row argmin ----
// grid: (64 row tiles, 8 code groups). Block: 128 rows x (8 tiles of 128 codes).
__global__ __launch_bounds__(256, 2)
void k_dist_argmin(const float* __restrict__ z, const float* __restrict__ cb) {
    __shared__ float As[8][128];
    __shared__ float Bs[8][132];   // +4 pad: conflict-free store pattern

    const int tid = threadIdx.x;
    const int bx  = blockIdx.x;            // rows bx*128 ..
    const int gy  = blockIdx.y;            // codes gy*1024 ..
    const int bb  = bx >> 1;               // batch index (128-row tile stays in one b)
    const int t0  = (bx & 1) * 128;
    const float* zbase = z + (size_t)bb * D_ * T_ + t0;

    const int r0 = (tid >> 4) * 8;         // 16 row-groups of 8
    const int c0 = (tid & 15) * 8;         // 16 col-groups of 8

    unsigned long long best[8];
    #pragma unroll
    for (int i = 0; i < 8; i++) best[i] = 0xFFFFFFFFFFFFFFFFull;

    for (int ct = 0; ct < 8; ct++) {
        const int k0 = gy * 1024 + ct * 128;

        float acc[8][8];
        #pragma unroll
        for (int i = 0; i < 8; i++)
            #pragma unroll
            for (int j = 0; j < 8; j++) acc[i][j] = 0.f;

        for (int d0 = 0; d0 < D_; d0 += 8) {
            // A tile: As[kk][r] = z[b, d0+kk, t0+r]  (coalesced: 128 contiguous t)
            #pragma unroll
            for (int p = 0; p < 4; p++) {
                int idx = tid + p * 256;
                int kk = idx >> 7, r = idx & 127;
                As[kk][r] = zbase[(d0 + kk) * T_ + r];
            }
            // B tile: Bs[kk][c] = cb[k0+c, d0+kk] (8 contiguous d per code)
            #pragma unroll
            for (int p = 0; p < 4; p++) {
                int idx = tid + p * 256;
                int c = idx >> 3, kk = idx & 7;
                Bs[kk][c] = cb[(size_t)(k0 + c) * D_ + d0 + kk];
            }
            __syncthreads();

            #pragma unroll
            for (int kk = 0; kk < 8; kk++) {
                float a[8], bv[8];
                *(float4*)&a[0]  = *(const float4*)&As[kk][r0];
                *(float4*)&a[4]  = *(const float4*)&As[kk][r0 + 4];
                *(float4*)&bv[0] = *(const float4*)&Bs[kk][c0];
                *(float4*)&bv[4] = *(const float4*)&Bs[kk][c0 + 4];
                #pragma unroll
                for (int i = 0; i < 8; i++)
                    #pragma unroll
                    for (int j = 0; j < 8; j++)
                        acc[i][j] = fmaf(a[i], bv[j], acc[i][j]);
            }
            __syncthreads();
        }

        // epilogue: score = cnorm[k] - 2*dot ; packed argmin (ties -> lowest idx)
        #pragma unroll
        for (int j = 0; j < 8; j++) {
            int k = k0 + c0 + j;
            float cn = __ldg(&g_cnorm[k]);
            #pragma unroll
            for (int i = 0; i < 8; i++) {
                float score = fmaf(-2.f, acc[i][j], cn);
                unsigned long long p =
                    ((unsigned long long)ford(score) << 32) | (unsigned int)k;
                if (p < best[i]) best[i] = p;
            }
        }
    }

    // reduce across the 16 col-threads sharing each row (contiguous 16 lanes)
    #pragma unroll
    for (int i = 0; i < 8; i++) {
        unsigned long long v = best[i];
        #pragma unroll
        for (int off = 8; off; off >>= 1) {
            unsigned long long o = __shfl_xor_sync(0xFFFFFFFFu, v, off);
            if (o < v) v = o;
        }
        if ((tid & 15) == 0)
            atomicMin(&g_best[bx * 128 + r0 + i], v);
    }
}

// ---- unpack winners: idx, counts, loss ----
__global__ void k_assign() {
    __shared__ float red[256];
    int n = blockIdx.x * 256 + threadIdx.x;   // grid 32
    unsigned long long v = g_best[n];
    int idx = (int)(v & 0xFFFFFFFFull);
    float score = funord((unsigned int)(v >> 32));
    g_idx[n] = idx;
    atomicAdd(&g_counts[idx], 1);
    float dist = score + g_znorm[n];          // ||z-c||^2 of the winner
    red[threadIdx.x] = dist;
    __syncthreads();
    for (int s = 128; s; s >>= 1) {
        if (threadIdx.x < s) red[threadIdx.x] += red[threadIdx.x + s];
        __syncthreads();
    }
    if (!threadIdx.x) atomicAdd(&g_loss, red[0]);
}

// ---- gather + transpose: out[b,d,t] = codebook[idx[b*T+t], d] ----
// grid (32, 4): y picks a 128-wide d-chunk for more parallelism
__global__ void k_gather(const float* __restrict__ cb, float* __restrict__ out) {
    int n = blockIdx.x * 256 + threadIdx.x;
    int b = n >> 8, t = n & 255;
    int dlo = blockIdx.y * 128;
    const float* row = cb + (size_t)g_idx[n] * D_ + dlo;
    float* obase = out + (size_t)b * D_ * T_ + (size_t)dlo * T_ + t;
    #pragma unroll 8
    for (int d = 0; d < 128; d++) obase[d * T_] = row[d];   // writes coalesced
}

// ---- perplexity + loss scalars ----
__global__ void k_final(float* __restrict__ out, int out_size) {
    __shared__ float red[256];
    float s = 0.f;
    for (int k = threadIdx.x; k < KCODE; k += 256) {
        float p = (float)g_counts[k] / (float)NVEC;
        s += p * logf(p + 1e-10f);
    }
    red[threadIdx.x] = s;
    __syncthreads();
    for (int st = 128; st; st >>= 1) {
        if (threadIdx.x < st) red[threadIdx.x] += red[threadIdx.x + st];
        __syncthreads();
    }
    if (!threadIdx.x) {
        out[out_size - 2] = 0.25f * g_loss / (float)(NVEC * D_);  // ALPHA*BETA*mean
        out[out_size - 1] = expf(-red[0]);
    }
}

extern "C" void kernel_launch(void* const* d_in, const int* in_sizes, int n_in,
                              void* d_out, int out_size) {
    const float* z  = (const float*)d_in[0];   // (B, D, T) fp32
    const float* cb = (const float*)d_in[1];   // (K, D) fp32
    float* out = (float*)d_out;                // [z_q (B*D*T)] [vq_loss] [perplexity]

    k_init<<<32, 256>>>();
    k_cnorm<<<KCODE / 8, 256>>>(cb);
    k_znorm<<<NVEC / 256, 256>>>(z);

    dim3 g(64, 8);
    k_dist_argmin<<<g, 256>>>(z, cb);

    k_assign<<<32, 256>>>();
    dim3 gg(32, 4);
    k_gather<<<gg, 256>>>(cb, out);
    k_final<<<1, 256>>>(out, out_size);
}

// round 5
// speedup vs baseline: 1.1399x; 1.1399x over previous
#include <cuda_runtime.h>
#include <cuda_bf16.h>
#include <math.h>
#include <stdint.h>

#define B_    32
#define T_    256
#define D_    512
#define NVEC  8192     // B_*T_
#define KCODE 8192
#define KH    1536     // expanded K: 3 slots per d: [z1,z1,z2] x [c1,c2,c1]
#define NTILES 64      // 64 code tiles of 128
#define NSTAGE 48      // KH/32

typedef unsigned long long u64;
typedef unsigned int u32;

// ---------------- device scratch ----------------
__device__ __align__(16) __nv_bfloat16 g_A[(size_t)NVEC * KH];    // 24MB split z
__device__ __align__(16) __nv_bfloat16 g_Bm[(size_t)KCODE * KH];  // 24MB split codebook
__device__ u64   g_m1[(size_t)NTILES * NVEC];                     // per-tile packed min
__device__ float g_m2[(size_t)NTILES * NVEC];                     // per-tile 2nd-min score
__device__ u64   g_best[NVEC];
__device__ float g_cnorm[KCODE];
__device__ int   g_flag[NVEC];
__device__ int   g_idx[NVEC];
__device__ int   g_counts[KCODE];
__device__ float g_loss;
__device__ u32 g_Mz, g_Mc, g_Mz2, g_Mc2, g_Sz2, g_Sc2, g_Szr, g_Scr;

// ---------------- ordered float packing ----------------
__device__ __forceinline__ u32 ford(float f) {
    u32 u = __float_as_uint(f);
    return u ^ ((u >> 31) ? 0xFFFFFFFFu : 0x80000000u);
}
__device__ __forceinline__ float funord(u32 u) {
    u ^= ((u >> 31) ? 0x80000000u : 0xFFFFFFFFu);
    return __uint_as_float(u);
}
#define P1INIT 0xFF800000FFFFFFFFull   // packed(+INF, idx 0xFFFFFFFF)

__device__ __forceinline__ u32 smem_u32(const void* p) {
    u32 a;
    asm("{ .reg .u64 t; cvta.to.shared.u64 t, %1; cvt.u32.u64 %0, t; }" : "=r"(a) : "l"(p));
    return a;
}
__device__ __forceinline__ void cp16(u32 dst, const void* src) {
    asm volatile("cp.async.cg.shared.global [%0], [%1], 16;" :: "r"(dst), "l"(src) : "memory");
}
__device__ __forceinline__ void ldsm4(u32* r, u32 addr) {
    asm volatile("ldmatrix.sync.aligned.m8n8.x4.shared.b16 {%0,%1,%2,%3}, [%4];"
        : "=r"(r[0]), "=r"(r[1]), "=r"(r[2]), "=r"(r[3]) : "r"(addr));
}
__device__ __forceinline__ void mma16816(float* c, const u32* a, u32 b0, u32 b1) {
    asm volatile("mma.sync.aligned.m16n8k16.row.col.f32.bf16.bf16.f32 "
        "{%0,%1,%2,%3}, {%4,%5,%6,%7}, {%8,%9}, {%0,%1,%2,%3};"
        : "+f"(c[0]), "+f"(c[1]), "+f"(c[2]), "+f"(c[3])
        : "r"(a[0]), "r"(a[1]), "r"(a[2]), "r"(a[3]), "r"(b0), "r"(b1));
}
// store-side swizzle: safe because XOR term derives from row bits and only touches bits 4-5
#define SWZ(o) ((o) ^ (((o) >> 3) & 0x30))

// ---------------- reset ----------------
__global__ void k_init() {
    int i = blockIdx.x * 256 + threadIdx.x;
    if (i < KCODE) g_counts[i] = 0;
    if (i == 0) {
        g_loss = 0.f;
        g_Mz = g_Mc = g_Mz2 = g_Mc2 = g_Sz2 = g_Sc2 = g_Szr = g_Scr = 0u;
    }
}

// ---------------- split z: slots [z1, z1, z2] ----------------
__global__ void k_prep_z(const float* __restrict__ z) {
    int n = blockIdx.x * 256 + threadIdx.x;
    int b = n >> 8, t = n & 255;
    const float* zb = z + (size_t)b * D_ * T_ + t;
    __nv_bfloat16* arow = g_A + (size_t)n * KH;
    float S2 = 0.f, Sr = 0.f, M = 0.f, M2 = 0.f;
    for (int d0 = 0; d0 < D_; d0 += 8) {
        union { unsigned short u[24]; uint4 q[3]; } w;
        #pragma unroll
        for (int j = 0; j < 8; j++) {
            float v = zb[(d0 + j) * T_];
            __nv_bfloat16 h1 = __float2bfloat16(v);
            float f1 = __bfloat162float(h1);
            float res = v - f1;
            __nv_bfloat16 h2 = __float2bfloat16(res);
            float f2 = __bfloat162float(h2);
            float r = res - f2;
            S2 += fabsf(f2); Sr += fabsf(r);
            M = fmaxf(M, fabsf(v)); M2 = fmaxf(M2, fabsf(f2));
            w.u[3 * j + 0] = __bfloat16_as_ushort(h1);
            w.u[3 * j + 1] = __bfloat16_as_ushort(h1);
            w.u[3 * j + 2] = __bfloat16_as_ushort(h2);
        }
        uint4* dst = (uint4*)(arow + 3 * d0);
        dst[0] = w.q[0]; dst[1] = w.q[1]; dst[2] = w.q[2];
    }
    atomicMax(&g_Sz2, __float_as_uint(S2));
    atomicMax(&g_Szr, __float_as_uint(Sr));
    atomicMax(&g_Mz,  __float_as_uint(M));
    atomicMax(&g_Mz2, __float_as_uint(M2));
}

// ---------------- split codebook: slots [c1, c2, c1] + cnorm ----------------
__global__ void k_prep_cb(const float* __restrict__ cb) {
    int code = (blockIdx.x * 256 + threadIdx.x) >> 5;
    int lane = threadIdx.x & 31;
    if (code >= KCODE) return;
    const float* row = cb + (size_t)code * D_;
    __nv_bfloat16* brow = g_Bm + (size_t)code * KH;
    float S2 = 0.f, Sr = 0.f, M = 0.f, M2 = 0.f, N2 = 0.f;
    #pragma unroll
    for (int pass = 0; pass < 2; pass++) {
        int d0 = pass * 256 + lane * 8;
        float4 va = *(const float4*)(row + d0);
        float4 vb = *(const float4*)(row + d0 + 4);
        float vv[8] = { va.x, va.y, va.z, va.w, vb.x, vb.y, vb.z, vb.w };
        union { unsigned short u[24]; uint4 q[3]; } w;
        #pragma unroll
        for (int j = 0; j < 8; j++) {
            float v = vv[j];
            N2 = fmaf(v, v, N2);
            __nv_bfloat16 h1 = __float2bfloat16(v);
            float f1 = __bfloat162float(h1);
            float res = v - f1;
            __nv_bfloat16 h2 = __float2bfloat16(res);
            float f2 = __bfloat162float(h2);
            float r = res - f2;
            S2 += fabsf(f2); Sr += fabsf(r);
            M = fmaxf(M, fabsf(v)); M2 = fmaxf(M2, fabsf(f2));
            w.u[3 * j + 0] = __bfloat16_as_ushort(h1);
            w.u[3 * j + 1] = __bfloat16_as_ushort(h2);
            w.u[3 * j + 2] = __bfloat16_as_ushort(h1);
        }
        uint4* dst = (uint4*)(brow + 3 * d0);
        dst[0] = w.q[0]; dst[1] = w.q[1]; dst[2] = w.q[2];
    }
    #pragma unroll
    for (int o = 16; o; o >>= 1) {
        N2 += __shfl_xor_sync(0xFFFFFFFFu, N2, o);
        S2 += __shfl_xor_sync(0xFFFFFFFFu, S2, o);
        Sr += __shfl_xor_sync(0xFFFFFFFFu, Sr, o);
        M   = fmaxf(M,  __shfl_xor_sync(0xFFFFFFFFu, M,  o));
        M2  = fmaxf(M2, __shfl_xor_sync(0xFFFFFFFFu, M2, o));
    }
    if (!lane) {
        g_cnorm[code] = N2;
        atomicMax(&g_Sc2, __float_as_uint(S2));
        atomicMax(&g_Scr, __float_as_uint(Sr));
        atomicMax(&g_Mc,  __float_as_uint(M));
        atomicMax(&g_Mc2, __float_as_uint(M2));
    }
}

// ---------------- bf16 mma.sync GEMM (256x128 CTA tile, K=1536) + top-2 epilogue ----------------
__global__ __launch_bounds__(512, 1)
void k_gemm() {
    __shared__ __align__(128) char smem_raw[49152];   // A: 2x16KB | B: 2x8KB
    const int tid = threadIdx.x;
    const int wid = tid >> 5, lane = tid & 31;
    const int wr = wid >> 2, wc = wid & 3;            // 4x4 warp grid
    const int rt = blockIdx.x;                        // 256 z-rows
    const int ntb = blockIdx.y;                       // 128 codes
    const u32 uSA = smem_u32(smem_raw);
    const u32 uSB = uSA + 32768;

    const __nv_bfloat16* Abase = g_A  + (size_t)rt  * 256 * KH;
    const __nv_bfloat16* Bbase = g_Bm + (size_t)ntb * 128 * KH;

    // cp.async per-thread src/dst (A: 2 chunks, B: 1 chunk of 16B per stage)
    const __nv_bfloat16* aSrc0 = Abase + (size_t)(tid >> 2) * KH + (tid & 3) * 8;
    const __nv_bfloat16* aSrc1 = aSrc0 + (size_t)128 * KH;
    const __nv_bfloat16* bSrc  = Bbase + (size_t)(tid >> 2) * KH + (tid & 3) * 8;
    const u32 aDst0 = uSA + SWZ((u32)((tid >> 2) * 64 + (tid & 3) * 16));
    const u32 aDst1 = uSA + SWZ((u32)(((tid >> 2) + 128) * 64 + (tid & 3) * 16));
    const u32 bDst  = uSB + SWZ((u32)((tid >> 2) * 64 + (tid & 3) * 16));

    // ldmatrix: row-byte bases (UNswizzled) + per-use chunk XOR
    const u32 lswz = ((((u32)lane & 15u) >> 1) & 3u) << 4;  // = ((row>>1)&3)<<4 for these rows
    const u32 aRow = uSA + (u32)(wr * 64 + (lane & 15)) * 64;
    const u32 bRow = uSB + (u32)(wc * 32 + (lane & 15)) * 64;
    const u32 chnk = ((u32)lane >> 4) * 16;                 // 0 or 16

    float c[4][4][4];
    #pragma unroll
    for (int i = 0; i < 4; i++)
        #pragma unroll
        for (int j = 0; j < 4; j++)
            #pragma unroll
            for (int k = 0; k < 4; k++) c[i][j][k] = 0.f;

    // prologue: stage 0
    cp16(aDst0, aSrc0); cp16(aDst1, aSrc1); cp16(bDst, bSrc);
    asm volatile("cp.async.commit_group;" ::: "memory");

    for (int s = 0; s < NSTAGE; s++) {
        if (s + 1 < NSTAGE) {
            const int nb = (s + 1) & 1;
            const int ke = (s + 1) * 32;
            cp16(aDst0 + nb * 16384, aSrc0 + ke);
            cp16(aDst1 + nb * 16384, aSrc1 + ke);
            cp16(bDst  + nb * 8192,  bSrc  + ke);
            asm volatile("cp.async.commit_group;" ::: "memory");
            asm volatile("cp.async.wait_group 1;" ::: "memory");
        } else {
            asm volatile("cp.async.wait_group 0;" ::: "memory");
        }
        __syncthreads();

        const u32 bufA = (s & 1) * 16384, bufB = (s & 1) * 8192;
        #pragma unroll
        for (int kh = 0; kh < 2; kh++) {
            const u32 cx = (chnk + kh * 32) ^ lswz;   // stays within the 64B row
            u32 a[4][4], b[2][4];
            #pragma unroll
            for (int mf = 0; mf < 4; mf++)
                ldsm4(a[mf], aRow + bufA + mf * 1024 + cx);
            #pragma unroll
            for (int nb2 = 0; nb2 < 2; nb2++)
                ldsm4(b[nb2], bRow + bufB + nb2 * 1024 + cx);   // B: non-trans (fix)
            #pragma unroll
            for (int mf = 0; mf < 4; mf++)
                #pragma unroll
                for (int nf = 0; nf < 4; nf++)
                    mma16816(c[mf][nf], a[mf], b[nf >> 1][nf & 1], b[nf >> 1][(nf & 1) + 2]);
        }
        __syncthreads();
    }

    // ---- epilogue: per-row top-2 over this 128-code tile ----
    u64*   sp1 = (u64*)smem_raw;                   // [256][4]
    float* ss2 = (float*)(smem_raw + 256 * 4 * 8); // [256][4]

    float cn[4][2];
    #pragma unroll
    for (int nf = 0; nf < 4; nf++)
        #pragma unroll
        for (int j = 0; j < 2; j++)
            cn[nf][j] = __ldg(&g_cnorm[ntb * 128 + wc * 32 + nf * 8 + (lane & 3) * 2 + j]);

    #pragma unroll
    for (int mf = 0; mf < 4; mf++) {
        #pragma unroll
        for (int h = 0; h < 2; h++) {
            u64 p1 = P1INIT; float s2 = __int_as_float(0x7f800000);
            #pragma unroll
            for (int nf = 0; nf < 4; nf++) {
                #pragma unroll
                for (int j = 0; j < 2; j++) {
                    float sc = fmaf(-2.f, c[mf][nf][h * 2 + j], cn[nf][j]);
                    int k = ntb * 128 + wc * 32 + nf * 8 + (lane & 3) * 2 + j;
                    u64 p = ((u64)ford(sc) << 32) | (u32)k;
                    if (p < p1) { s2 = fminf(s2, funord((u32)(p1 >> 32))); p1 = p; }
                    else        { s2 = fminf(s2, sc); }
                }
            }
            #pragma unroll
            for (int off = 1; off <= 2; off <<= 1) {
                u64 po = __shfl_xor_sync(0xFFFFFFFFu, p1, off);
                float s2o = __shfl_xor_sync(0xFFFFFFFFu, s2, off);
                float s1a = funord((u32)(p1 >> 32)), s1b = funord((u32)(po >> 32));
                s2 = fminf(fminf(s2, s2o), fmaxf(s1a, s1b));
                if (po < p1) p1 = po;
            }
            if ((lane & 3) == 0) {
                int row = wr * 64 + mf * 16 + (lane >> 2) + h * 8;
                sp1[row * 4 + wc] = p1;
                ss2[row * 4 + wc] = s2;
            }
        }
    }
    __syncthreads();
    if (tid < 256) {
        u64 p1 = sp1[tid * 4]; float s2 = ss2[tid * 4];
        #pragma unroll
        for (int w = 1; w < 4; w++) {
            u64 po = sp1[tid * 4 + w]; float s2o = ss2[tid * 4 + w];
            float s1a = funord((u32)(p1 >> 32)), s1b = funord((u32)(po >> 32));
            s2 = fminf(fminf(s2, s2o), fmaxf(s1a, s1b));
            if (po < p1) p1 = po;
        }
        g_m1[(size_t)ntb * NVEC + rt * 256 + tid] = p1;
        g_m2[(size_t)ntb * NVEC + rt * 256 + tid] = s2;
    }
}

// ---------------- merge tiles, flag ambiguous rows ----------------
__global__ void k_reduce() {
    int row = blockIdx.x * 256 + threadIdx.x;
    float Mz  = __uint_as_float(g_Mz),  Mc  = __uint_as_float(g_Mc);
    float Mz2 = __uint_as_float(g_Mz2), Mc2 = __uint_as_float(g_Mc2);
    float Sz2 = __uint_as_float(g_Sz2), Sc2 = __uint_as_float(g_Sc2);
    float Szr = __uint_as_float(g_Szr), Scr = __uint_as_float(g_Scr);
    float errdot = fminf(Mc2 * Sz2, Mz2 * Sc2) + Mc * Szr + Mz * Scr + Mc2 * Szr;
    float TH = 2.f * errdot + 0.03f;   // + fp32 accumulation slack

    u64 p1 = P1INIT;
    float s1 = __int_as_float(0x7f800000), s2 = s1;
    for (int nt = 0; nt < NTILES; nt++) {
        u64 q = g_m1[(size_t)nt * NVEC + row];
        float a = funord((u32)(q >> 32));
        float b = g_m2[(size_t)nt * NVEC + row];
        if (a < s1) { s2 = s1; s1 = a; } else { s2 = fminf(s2, a); }
        if (q < p1) p1 = q;
        s2 = fminf(s2, b);
    }
    if (s2 - s1 < TH) { g_flag[row] = 1; g_best[row] = 0xFFFFFFFFFFFFFFFFull; }
    else              { g_flag[row] = 0; g_best[row] = p1; }
}

// ---------------- exact fp32 rescan for flagged rows ----------------
__global__ __launch_bounds__(256) void k_rescue(const float* __restrict__ z, const float* __restrict__ cb) {
    __shared__ float zrow[D_];
    __shared__ int sflag[128];
    __shared__ int sany;
    const int tid = threadIdx.x, wid = tid >> 5, lane = tid & 31;
    const int rt = blockIdx.x, cy = blockIdx.y;
    if (tid == 0) sany = 0;
    __syncthreads();
    if (tid < 128) { int f = g_flag[rt * 128 + tid]; sflag[tid] = f; if (f) sany = 1; }
    __syncthreads();
    if (!sany) return;
    for (int r = 0; r < 128; r++) {
        if (!sflag[r]) continue;
        const int row = rt * 128 + r, b = row >> 8, t = row & 255;
        for (int d = tid; d < D_; d += 256)
            zrow[d] = z[(size_t)b * D_ * T_ + (size_t)d * T_ + t];
        __syncthreads();
        u64 loc = 0xFFFFFFFFFFFFFFFFull;
        for (int i = 0; i < 128; i++) {
            const int code = cy * 1024 + wid * 128 + i;
            const float* crow = cb + (size_t)code * D_;
            float dot = 0.f;
            #pragma unroll
            for (int j = 0; j < 16; j++)
                dot = fmaf(crow[lane + j * 32], zrow[lane + j * 32], dot);
            #pragma unroll
            for (int o = 16; o; o >>= 1) dot += __shfl_xor_sync(0xFFFFFFFFu, dot, o);
            if (!lane) {
                float sc = fmaf(-2.f, dot, g_cnorm[code]);
                u64 p = ((u64)ford(sc) << 32) | (u32)code;
                if (p < loc) loc = p;
            }
        }
        if (!lane) atomicMin(&g_best[row], loc);
        __syncthreads();
    }
}

// ---------------- counts ----------------
__global__ void k_counts() {
    int n = blockIdx.x * 256 + threadIdx.x;
    int idx = (int)(g_best[n] & 0xFFFFFFFFull);
    g_idx[n] = idx;
    atomicAdd(&g_counts[idx], 1);
}

// ---------------- gather + transpose + loss ----------------
__global__ void k_gather(const float* __restrict__ z, const float* __restrict__ cb, float* __restrict__ out) {
    __shared__ float red[256];
    int n = blockIdx.x * 256 + threadIdx.x;
    int b = n >> 8, t = n & 255;
    int dlo = blockIdx.y * 128;
    const float* crow = cb + (size_t)g_idx[n] * D_ + dlo;
    const float* zb = z + (size_t)b * D_ * T_ + (size_t)dlo * T_ + t;
    float* ob = out + (size_t)b * D_ * T_ + (size_t)dlo * T_ + t;
    float s = 0.f;
    #pragma unroll 8
    for (int d = 0; d < 128; d++) {
        float cv = __ldg(crow + d);
        float zv = zb[d * T_];
        ob[d * T_] = cv;
        float df = cv - zv;
        s = fmaf(df, df, s);
    }
    red[threadIdx.x] = s;
    __syncthreads();
    for (int st = 128; st; st >>= 1) {
        if (threadIdx.x < st) red[threadIdx.x] += red[threadIdx.x + st];
        __syncthreads();
    }
    if (!threadIdx.x) atomicAdd(&g_loss, red[0]);
}

// ---------------- scalars ----------------
__global__ void k_final(float* __restrict__ out, int out_size) {
    __shared__ float red[256];
    float s = 0.f;
    for (int k = threadIdx.x; k < KCODE; k += 256) {
        float p = (float)g_counts[k] / (float)NVEC;
        s += p * logf(p + 1e-10f);
    }
    red[threadIdx.x] = s;
    __syncthreads();
    for (int st = 128; st; st >>= 1) {
        if (threadIdx.x < st) red[threadIdx.x] += red[threadIdx.x + st];
        __syncthreads();
    }
    if (!threadIdx.x) {
        out[out_size - 2] = 0.25f * g_loss / (float)((size_t)NVEC * D_);
        out[out_size - 1] = expf(-red[0]);
    }
}

extern "C" void kernel_launch(void* const* d_in, const int* in_sizes, int n_in,
                              void* d_out, int out_size) {
    const float* z  = (const float*)d_in[0];   // (B, D, T) fp32
    const float* cb = (const float*)d_in[1];   // (K, D) fp32
    float* out = (float*)d_out;

    k_init<<<32, 256>>>();
    k_prep_z<<<32, 256>>>(z);
    k_prep_cb<<<1024, 256>>>(cb);
    k_gemm<<<dim3(32, 64), 512>>>();
    k_reduce<<<32, 256>>>();
    k_rescue<<<dim3(64, 8), 256>>>(z, cb);
    k_counts<<<32, 256>>>();
    k_gather<<<dim3(32, 4), 256>>>(z, cb, out);
    k_final<<<1, 256>>>(out, out_size);
}

// round 7
// speedup vs baseline: 3.3233x; 2.9155x over previous
#include <cuda_runtime.h>
#include <cuda_bf16.h>
#include <math.h>
#include <stdint.h>

#define B_    32
#define T_    256
#define D_    512
#define NVEC  8192     // B_*T_
#define KCODE 8192
#define KS    512      // single bf16 slot per dim
#define NTILES 64      // 64 code tiles of 128
#define NST   16       // K stages of 32
// 4-stage cp.async pipeline

typedef unsigned long long u64;
typedef unsigned int u32;

// ---------------- device scratch ----------------
__device__ __align__(16) __nv_bfloat16 g_A[(size_t)NVEC * KS];    // 8MB bf16 z
__device__ __align__(16) __nv_bfloat16 g_Bm[(size_t)KCODE * KS];  // 8MB bf16 codebook
__device__ u64   g_m1[(size_t)NTILES * NVEC];                     // per-tile packed min (approx)
__device__ float g_rowmin[NVEC];                                  // per-row approx min score
__device__ u64   g_best[NVEC];
__device__ float g_cnorm[KCODE];
__device__ int   g_idx[NVEC];
__device__ int   g_counts[KCODE];
__device__ float g_loss;
__device__ u32 g_n1z, g_n2z, g_n1c, g_n2c;   // max squared norms: ||z1||,||z2||,||c1||,||c2||

// ---------------- ordered float packing ----------------
__device__ __forceinline__ u32 ford(float f) {
    u32 u = __float_as_uint(f);
    return u ^ ((u >> 31) ? 0xFFFFFFFFu : 0x80000000u);
}
__device__ __forceinline__ float funord(u32 u) {
    u ^= ((u >> 31) ? 0x80000000u : 0xFFFFFFFFu);
    return __uint_as_float(u);
}
#define P1INIT 0xFF800000FFFFFFFFull

__device__ __forceinline__ u32 smem_u32(const void* p) {
    u32 a;
    asm("{ .reg .u64 t; cvta.to.shared.u64 t, %1; cvt.u32.u64 %0, t; }" : "=r"(a) : "l"(p));
    return a;
}
__device__ __forceinline__ void cp16(u32 dst, const void* src) {
    asm volatile("cp.async.cg.shared.global [%0], [%1], 16;" :: "r"(dst), "l"(src) : "memory");
}
__device__ __forceinline__ void ldsm4(u32* r, u32 addr) {
    asm volatile("ldmatrix.sync.aligned.m8n8.x4.shared.b16 {%0,%1,%2,%3}, [%4];"
        : "=r"(r[0]), "=r"(r[1]), "=r"(r[2]), "=r"(r[3]) : "r"(addr));
}
__device__ __forceinline__ void mma16816(float* c, const u32* a, u32 b0, u32 b1) {
    asm volatile("mma.sync.aligned.m16n8k16.row.col.f32.bf16.bf16.f32 "
        "{%0,%1,%2,%3}, {%4,%5,%6,%7}, {%8,%9}, {%0,%1,%2,%3};"
        : "+f"(c[0]), "+f"(c[1]), "+f"(c[2]), "+f"(c[3])
        : "r"(a[0]), "r"(a[1]), "r"(a[2]), "r"(a[3]), "r"(b0), "r"(b1));
}
#define SWZ(o) ((o) ^ (((o) >> 3) & 0x30))

// ---------------- reset ----------------
__global__ void k_init() {
    int i = blockIdx.x * 256 + threadIdx.x;
    if (i < KCODE) g_counts[i] = 0;
    if (i == 0) { g_loss = 0.f; g_n1z = g_n2z = g_n1c = g_n2c = 0u; }
}

// ---------------- z -> bf16 + residual norm tracking ----------------
__global__ void k_prep_z(const float* __restrict__ z) {
    int n = blockIdx.x * 256 + threadIdx.x;
    int b = n >> 8, t = n & 255;
    const float* zb = z + (size_t)b * D_ * T_ + t;
    __nv_bfloat16* arow = g_A + (size_t)n * KS;
    float n1 = 0.f, n2 = 0.f;
    for (int d0 = 0; d0 < D_; d0 += 8) {
        union { unsigned short u[8]; uint4 q; } w;
        #pragma unroll
        for (int j = 0; j < 8; j++) {
            float v = zb[(d0 + j) * T_];
            __nv_bfloat16 h1 = __float2bfloat16(v);
            float f1 = __bfloat162float(h1);
            float r = v - f1;
            n1 = fmaf(f1, f1, n1);
            n2 = fmaf(r, r, n2);
            w.u[j] = __bfloat16_as_ushort(h1);
        }
        *(uint4*)(arow + d0) = w.q;
    }
    atomicMax(&g_n1z, __float_as_uint(n1));
    atomicMax(&g_n2z, __float_as_uint(n2));
}

// ---------------- codebook -> bf16 + cnorm + residual norms ----------------
__global__ void k_prep_cb(const float* __restrict__ cb) {
    int code = (blockIdx.x * 256 + threadIdx.x) >> 5;
    int lane = threadIdx.x & 31;
    if (code >= KCODE) return;
    const float* row = cb + (size_t)code * D_;
    __nv_bfloat16* brow = g_Bm + (size_t)code * KS;
    float n1 = 0.f, n2 = 0.f, N2 = 0.f;
    #pragma unroll
    for (int pass = 0; pass < 2; pass++) {
        int d0 = pass * 256 + lane * 8;
        float4 va = *(const float4*)(row + d0);
        float4 vb = *(const float4*)(row + d0 + 4);
        float vv[8] = { va.x, va.y, va.z, va.w, vb.x, vb.y, vb.z, vb.w };
        union { unsigned short u[8]; uint4 q; } w;
        #pragma unroll
        for (int j = 0; j < 8; j++) {
            float v = vv[j];
            N2 = fmaf(v, v, N2);
            __nv_bfloat16 h1 = __float2bfloat16(v);
            float f1 = __bfloat162float(h1);
            float r = v - f1;
            n1 = fmaf(f1, f1, n1);
            n2 = fmaf(r, r, n2);
            w.u[j] = __bfloat16_as_ushort(h1);
        }
        *(uint4*)(brow + d0) = w.q;
    }
    #pragma unroll
    for (int o = 16; o; o >>= 1) {
        N2 += __shfl_xor_sync(0xFFFFFFFFu, N2, o);
        n1 += __shfl_xor_sync(0xFFFFFFFFu, n1, o);
        n2 += __shfl_xor_sync(0xFFFFFFFFu, n2, o);
    }
    if (!lane) {
        g_cnorm[code] = N2;
        atomicMax(&g_n1c, __float_as_uint(n1));
        atomicMax(&g_n2c, __float_as_uint(n2));
    }
}

// ---------------- bf16 mma.sync GEMM (256x128 CTA tile, K=512, 4-stage) ----------------
__global__ __launch_bounds__(512, 1)
void k_gemm() {
    extern __shared__ __align__(128) char smem_raw[];   // A: 4x16KB | B: 4x8KB = 96KB
    const int tid = threadIdx.x;
    const int wid = tid >> 5, lane = tid & 31;
    const int wr = wid >> 2, wc = wid & 3;            // 4x4 warp grid
    const int rt = blockIdx.x;                        // 256 z-rows
    const int ntb = blockIdx.y;                       // 128 codes
    const u32 uSA = smem_u32(smem_raw);
    const u32 uSB = uSA + 65536;

    const __nv_bfloat16* Abase = g_A  + (size_t)rt  * 256 * KS;
    const __nv_bfloat16* Bbase = g_Bm + (size_t)ntb * 128 * KS;

    const __nv_bfloat16* aSrc0 = Abase + (size_t)(tid >> 2) * KS + (tid & 3) * 8;
    const __nv_bfloat16* aSrc1 = aSrc0 + (size_t)128 * KS;
    const __nv_bfloat16* bSrc  = Bbase + (size_t)(tid >> 2) * KS + (tid & 3) * 8;
    const u32 aDst0 = uSA + SWZ((u32)((tid >> 2) * 64 + (tid & 3) * 16));
    const u32 aDst1 = uSA + SWZ((u32)(((tid >> 2) + 128) * 64 + (tid & 3) * 16));
    const u32 bDst  = uSB + SWZ((u32)((tid >> 2) * 64 + (tid & 3) * 16));

    const u32 lswz = ((((u32)lane & 15u) >> 1) & 3u) << 4;
    const u32 aRow = uSA + (u32)(wr * 64 + (lane & 15)) * 64;
    const u32 bRow = uSB + (u32)(wc * 32 + (lane & 15)) * 64;
    const u32 chnk = ((u32)lane >> 4) * 16;

    float c[4][4][4];
    #pragma unroll
    for (int i = 0; i < 4; i++)
        #pragma unroll
        for (int j = 0; j < 4; j++)
            #pragma unroll
            for (int k = 0; k < 4; k++) c[i][j][k] = 0.f;

    // prologue: stages 0..2
    #pragma unroll
    for (int p = 0; p < 3; p++) {
        cp16(aDst0 + p * 16384, aSrc0 + p * 32);
        cp16(aDst1 + p * 16384, aSrc1 + p * 32);
        cp16(bDst  + p * 8192,  bSrc  + p * 32);
        asm volatile("cp.async.commit_group;" ::: "memory");
    }

    for (int s = 0; s < NST; s++) {
        if (s < NST - 2)       asm volatile("cp.async.wait_group 2;" ::: "memory");
        else if (s == NST - 2) asm volatile("cp.async.wait_group 1;" ::: "memory");
        else                   asm volatile("cp.async.wait_group 0;" ::: "memory");
        __syncthreads();

        if (s + 3 < NST) {
            const int p = s + 3, pb = p & 3;
            cp16(aDst0 + pb * 16384, aSrc0 + p * 32);
            cp16(aDst1 + pb * 16384, aSrc1 + p * 32);
            cp16(bDst  + pb * 8192,  bSrc  + p * 32);
            asm volatile("cp.async.commit_group;" ::: "memory");
        }

        const u32 bufA = (u32)(s & 3) * 16384, bufB = (u32)(s & 3) * 8192;
        #pragma unroll
        for (int kh = 0; kh < 2; kh++) {
            const u32 cx = (chnk + kh * 32) ^ lswz;
            u32 a[4][4], b[2][4];
            #pragma unroll
            for (int mf = 0; mf < 4; mf++)
                ldsm4(a[mf], aRow + bufA + mf * 1024 + cx);
            #pragma unroll
            for (int nb2 = 0; nb2 < 2; nb2++)
                ldsm4(b[nb2], bRow + bufB + nb2 * 1024 + cx);
            #pragma unroll
            for (int mf = 0; mf < 4; mf++)
                #pragma unroll
                for (int nf = 0; nf < 4; nf++)
                    mma16816(c[mf][nf], a[mf], b[nf >> 1][nf & 1], b[nf >> 1][(nf & 1) + 2]);
        }
    }
    __syncthreads();   // all smem reads done before epilogue reuse

    // ---- epilogue: per-row min over this 128-code tile ----
    u64* sp1 = (u64*)smem_raw;                     // [256][4]

    float cn[4][2];
    #pragma unroll
    for (int nf = 0; nf < 4; nf++)
        #pragma unroll
        for (int j = 0; j < 2; j++)
            cn[nf][j] = __ldg(&g_cnorm[ntb * 128 + wc * 32 + nf * 8 + (lane & 3) * 2 + j]);

    #pragma unroll
    for (int mf = 0; mf < 4; mf++) {
        #pragma unroll
        for (int h = 0; h < 2; h++) {
            u64 p1 = P1INIT;
            #pragma unroll
            for (int nf = 0; nf < 4; nf++) {
                #pragma unroll
                for (int j = 0; j < 2; j++) {
                    float sc = fmaf(-2.f, c[mf][nf][h * 2 + j], cn[nf][j]);
                    int k = ntb * 128 + wc * 32 + nf * 8 + (lane & 3) * 2 + j;
                    u64 p = ((u64)ford(sc) << 32) | (u32)k;
                    if (p < p1) p1 = p;
                }
            }
            #pragma unroll
            for (int off = 1; off <= 2; off <<= 1) {
                u64 po = __shfl_xor_sync(0xFFFFFFFFu, p1, off);
                if (po < p1) p1 = po;
            }
            if ((lane & 3) == 0) {
                int row = wr * 64 + mf * 16 + (lane >> 2) + h * 8;
                sp1[row * 4 + wc] = p1;
            }
        }
    }
    __syncthreads();
    if (tid < 256) {
        u64 p1 = sp1[tid * 4];
        #pragma unroll
        for (int w = 1; w < 4; w++) {
            u64 po = sp1[tid * 4 + w];
            if (po < p1) p1 = po;
        }
        g_m1[(size_t)ntb * NVEC + rt * 256 + tid] = p1;
    }
}

// ---------------- per-row approx min over tiles ----------------
__global__ void k_reduce() {
    int row = blockIdx.x * 256 + threadIdx.x;
    u64 p1 = 0xFFFFFFFFFFFFFFFFull;
    for (int nt = 0; nt < NTILES; nt++) {
        u64 q = g_m1[(size_t)nt * NVEC + row];
        if (q < p1) p1 = q;
    }
    g_rowmin[row] = funord((u32)(p1 >> 32));
    g_best[row] = 0xFFFFFFFFFFFFFFFFull;
}

// ---------------- exact fp32 rescan of candidate (row, tile) pairs ----------------
__global__ __launch_bounds__(256) void k_rescue(const float* __restrict__ z, const float* __restrict__ cb) {
    __shared__ float zrow[D_];
    __shared__ int list[128];
    __shared__ int cnt;
    const int tid = threadIdx.x, wid = tid >> 5, lane = tid & 31;
    const int rt = blockIdx.x, ct = blockIdx.y;    // 64 row tiles x 64 code tiles

    if (tid == 0) cnt = 0;
    __syncthreads();

    // deterministic candidate threshold from Cauchy-Schwarz residual bounds
    const float n1z = sqrtf(__uint_as_float(g_n1z)), n2z = sqrtf(__uint_as_float(g_n2z));
    const float n1c = sqrtf(__uint_as_float(g_n1c)), n2c = sqrtf(__uint_as_float(g_n2c));
    const float TH = 4.f * (n2z * n1c + n1z * n2c + n2z * n2c) + 0.3f;

    if (tid < 128) {
        int row = rt * 128 + tid;
        float sc = funord((u32)(g_m1[(size_t)ct * NVEC + row] >> 32));
        if (sc <= g_rowmin[row] + TH) { int p = atomicAdd(&cnt, 1); list[p] = row; }
    }
    __syncthreads();
    const int nv = cnt;
    if (!nv) return;

    for (int e = 0; e < nv; e++) {
        const int row = list[e], b = row >> 8, t = row & 255;
        for (int d = tid; d < D_; d += 256)
            zrow[d] = z[(size_t)b * D_ * T_ + (size_t)d * T_ + t];
        __syncthreads();
        u64 loc = 0xFFFFFFFFFFFFFFFFull;
        #pragma unroll 1
        for (int i = 0; i < 16; i++) {
            const int code = ct * 128 + wid * 16 + i;
            const float* crow = cb + (size_t)code * D_;
            float dot = 0.f;
            #pragma unroll
            for (int j = 0; j < 16; j++)
                dot = fmaf(crow[lane + j * 32], zrow[lane + j * 32], dot);
            #pragma unroll
            for (int o = 16; o; o >>= 1) dot += __shfl_xor_sync(0xFFFFFFFFu, dot, o);
            if (!lane) {
                float sc = fmaf(-2.f, dot, g_cnorm[code]);
                u64 p = ((u64)ford(sc) << 32) | (u32)code;
                if (p < loc) loc = p;
            }
        }
        if (!lane) atomicMin(&g_best[row], loc);
        __syncthreads();
    }
}

// ---------------- counts ----------------
__global__ void k_counts() {
    int n = blockIdx.x * 256 + threadIdx.x;
    int idx = (int)(g_best[n] & 0xFFFFFFFFull);
    g_idx[n] = idx;
    atomicAdd(&g_counts[idx], 1);
}

// ---------------- gather + transpose + loss ----------------
__global__ void k_gather(const float* __restrict__ z, const float* __restrict__ cb, float* __restrict__ out) {
    __shared__ float red[256];
    int n = blockIdx.x * 256 + threadIdx.x;
    int b = n >> 8, t = n & 255;
    int dlo = blockIdx.y * 128;
    const float* crow = cb + (size_t)g_idx[n] * D_ + dlo;
    const float* zb = z + (size_t)b * D_ * T_ + (size_t)dlo * T_ + t;
    float* ob = out + (size_t)b * D_ * T_ + (size_t)dlo * T_ + t;
    float s = 0.f;
    #pragma unroll 8
    for (int d = 0; d < 128; d++) {
        float cv = __ldg(crow + d);
        float zv = zb[d * T_];
        ob[d * T_] = cv;
        float df = cv - zv;
        s = fmaf(df, df, s);
    }
    red[threadIdx.x] = s;
    __syncthreads();
    for (int st = 128; st; st >>= 1) {
        if (threadIdx.x < st) red[threadIdx.x] += red[threadIdx.x + st];
        __syncthreads();
    }
    if (!threadIdx.x) atomicAdd(&g_loss, red[0]);
}

// ---------------- scalars ----------------
__global__ void k_final(float* __restrict__ out, int out_size) {
    __shared__ float red[256];
    float s = 0.f;
    for (int k = threadIdx.x; k < KCODE; k += 256) {
        float p = (float)g_counts[k] / (float)NVEC;
        s += p * logf(p + 1e-10f);
    }
    red[threadIdx.x] = s;
    __syncthreads();
    for (int st = 128; st; st >>= 1) {
        if (threadIdx.x < st) red[threadIdx.x] += red[threadIdx.x + st];
        __syncthreads();
    }
    if (!threadIdx.x) {
        out[out_size - 2] = 0.25f * g_loss / (float)((size_t)NVEC * D_);
        out[out_size - 1] = expf(-red[0]);
    }
}

extern "C" void kernel_launch(void* const* d_in, const int* in_sizes, int n_in,
                              void* d_out, int out_size) {
    const float* z  = (const float*)d_in[0];   // (B, D, T) fp32
    const float* cb = (const float*)d_in[1];   // (K, D) fp32
    float* out = (float*)d_out;

    cudaFuncSetAttribute(k_gemm, cudaFuncAttributeMaxDynamicSharedMemorySize, 98304);

    k_init<<<32, 256>>>();
    k_prep_z<<<32, 256>>>(z);
    k_prep_cb<<<1024, 256>>>(cb);
    k_gemm<<<dim3(32, 64), 512, 98304>>>();
    k_reduce<<<32, 256>>>();
    k_rescue<<<dim3(64, 64), 256>>>(z, cb);
    k_counts<<<32, 256>>>();
    k_gather<<<dim3(32, 4), 256>>>(z, cb, out);
    k_final<<<1, 256>>>(out, out_size);
}

// round 8
// speedup vs baseline: 4.2812x; 1.2883x over previous
#include <cuda_runtime.h>
#include <cuda_fp16.h>
#include <math.h>
#include <stdint.h>

#define B_    32
#define T_    256
#define D_    512
#define NVEC  8192     // B_*T_
#define KCODE 8192
#define KS    512      // single fp16 slot per dim
#define NTILES 64      // 64 code tiles of 128
#define NST   16       // K stages of 32

typedef unsigned long long u64;
typedef unsigned int u32;

// ---------------- device scratch ----------------
__device__ __align__(16) __half g_A[(size_t)NVEC * KS];    // 8MB fp16 z
__device__ __align__(16) __half g_Bm[(size_t)KCODE * KS];  // 8MB fp16 codebook
__device__ u64   g_m1[(size_t)NTILES * NVEC];              // per-tile packed min (approx)
__device__ float g_rowmin[NVEC];                           // per-row approx min score
__device__ float g_rowth[NVEC];                            // per-row candidate threshold
__device__ u64   g_best[NVEC];
__device__ float g_cnorm[KCODE];
__device__ float g_zn1[NVEC], g_zn2[NVEC];                 // per-row ||z1||, ||z_res||
__device__ int   g_counts[KCODE];
__device__ float g_loss;
__device__ u32 g_n1c, g_n2c;                               // global max ||c1||, ||c_res||

// ---------------- ordered float packing ----------------
__device__ __forceinline__ u32 ford(float f) {
    u32 u = __float_as_uint(f);
    return u ^ ((u >> 31) ? 0xFFFFFFFFu : 0x80000000u);
}
__device__ __forceinline__ float funord(u32 u) {
    u ^= ((u >> 31) ? 0x80000000u : 0xFFFFFFFFu);
    return __uint_as_float(u);
}
#define P1INIT 0xFF800000FFFFFFFFull

__device__ __forceinline__ u32 smem_u32(const void* p) {
    u32 a;
    asm("{ .reg .u64 t; cvta.to.shared.u64 t, %1; cvt.u32.u64 %0, t; }" : "=r"(a) : "l"(p));
    return a;
}
__device__ __forceinline__ void cp16(u32 dst, const void* src) {
    asm volatile("cp.async.cg.shared.global [%0], [%1], 16;" :: "r"(dst), "l"(src) : "memory");
}
__device__ __forceinline__ void ldsm4(u32* r, u32 addr) {
    asm volatile("ldmatrix.sync.aligned.m8n8.x4.shared.b16 {%0,%1,%2,%3}, [%4];"
        : "=r"(r[0]), "=r"(r[1]), "=r"(r[2]), "=r"(r[3]) : "r"(addr));
}
__device__ __forceinline__ void mma16816(float* c, const u32* a, u32 b0, u32 b1) {
    asm volatile("mma.sync.aligned.m16n8k16.row.col.f32.f16.f16.f32 "
        "{%0,%1,%2,%3}, {%4,%5,%6,%7}, {%8,%9}, {%0,%1,%2,%3};"
        : "+f"(c[0]), "+f"(c[1]), "+f"(c[2]), "+f"(c[3])
        : "r"(a[0]), "r"(a[1]), "r"(a[2]), "r"(a[3]), "r"(b0), "r"(b1));
}
#define SWZ(o) ((o) ^ (((o) >> 3) & 0x30))

// ---------------- reset ----------------
__global__ void k_init() {
    int i = blockIdx.x * 256 + threadIdx.x;
    if (i < KCODE) g_counts[i] = 0;
    if (i == 0) { g_loss = 0.f; g_n1c = 0u; g_n2c = 0u; }
}

// ---------------- z -> fp16 + per-row residual norms ----------------
__global__ void k_prep_z(const float* __restrict__ z) {
    int n = blockIdx.x * 256 + threadIdx.x;
    int b = n >> 8, t = n & 255;
    const float* zb = z + (size_t)b * D_ * T_ + t;
    __half* arow = g_A + (size_t)n * KS;
    float n1 = 0.f, n2 = 0.f;
    for (int d0 = 0; d0 < D_; d0 += 8) {
        union { unsigned short u[8]; uint4 q; } w;
        #pragma unroll
        for (int j = 0; j < 8; j++) {
            float v = zb[(d0 + j) * T_];
            __half h1 = __float2half_rn(v);
            float f1 = __half2float(h1);
            float r = v - f1;
            n1 = fmaf(f1, f1, n1);
            n2 = fmaf(r, r, n2);
            w.u[j] = __half_as_ushort(h1);
        }
        *(uint4*)(arow + d0) = w.q;
    }
    g_zn1[n] = sqrtf(n1);
    g_zn2[n] = sqrtf(n2);
}

// ---------------- codebook -> fp16 + cnorm + global residual norm maxes ----------------
__global__ void k_prep_cb(const float* __restrict__ cb) {
    int code = (blockIdx.x * 256 + threadIdx.x) >> 5;
    int lane = threadIdx.x & 31;
    if (code >= KCODE) return;
    const float* row = cb + (size_t)code * D_;
    __half* brow = g_Bm + (size_t)code * KS;
    float n1 = 0.f, n2 = 0.f, N2 = 0.f;
    #pragma unroll
    for (int pass = 0; pass < 2; pass++) {
        int d0 = pass * 256 + lane * 8;
        float4 va = *(const float4*)(row + d0);
        float4 vb = *(const float4*)(row + d0 + 4);
        float vv[8] = { va.x, va.y, va.z, va.w, vb.x, vb.y, vb.z, vb.w };
        union { unsigned short u[8]; uint4 q; } w;
        #pragma unroll
        for (int j = 0; j < 8; j++) {
            float v = vv[j];
            N2 = fmaf(v, v, N2);
            __half h1 = __float2half_rn(v);
            float f1 = __half2float(h1);
            float r = v - f1;
            n1 = fmaf(f1, f1, n1);
            n2 = fmaf(r, r, n2);
            w.u[j] = __half_as_ushort(h1);
        }
        *(uint4*)(brow + d0) = w.q;
    }
    #pragma unroll
    for (int o = 16; o; o >>= 1) {
        N2 += __shfl_xor_sync(0xFFFFFFFFu, N2, o);
        n1 += __shfl_xor_sync(0xFFFFFFFFu, n1, o);
        n2 += __shfl_xor_sync(0xFFFFFFFFu, n2, o);
    }
    if (!lane) {
        g_cnorm[code] = N2;
        atomicMax(&g_n1c, __float_as_uint(sqrtf(n1)));
        atomicMax(&g_n2c, __float_as_uint(sqrtf(n2)));
    }
}

// ---------------- fp16 mma.sync GEMM (256x128 CTA tile, K=512, 4-stage) ----------------
__global__ __launch_bounds__(512, 1)
void k_gemm() {
    extern __shared__ __align__(128) char smem_raw[];   // A: 4x16KB | B: 4x8KB = 96KB
    const int tid = threadIdx.x;
    const int wid = tid >> 5, lane = tid & 31;
    const int wr = wid >> 2, wc = wid & 3;            // 4x4 warp grid
    const int rt = blockIdx.x;                        // 256 z-rows
    const int ntb = blockIdx.y;                       // 128 codes
    const u32 uSA = smem_u32(smem_raw);
    const u32 uSB = uSA + 65536;

    const __half* Abase = g_A  + (size_t)rt  * 256 * KS;
    const __half* Bbase = g_Bm + (size_t)ntb * 128 * KS;

    const __half* aSrc0 = Abase + (size_t)(tid >> 2) * KS + (tid & 3) * 8;
    const __half* aSrc1 = aSrc0 + (size_t)128 * KS;
    const __half* bSrc  = Bbase + (size_t)(tid >> 2) * KS + (tid & 3) * 8;
    const u32 aDst0 = uSA + SWZ((u32)((tid >> 2) * 64 + (tid & 3) * 16));
    const u32 aDst1 = uSA + SWZ((u32)(((tid >> 2) + 128) * 64 + (tid & 3) * 16));
    const u32 bDst  = uSB + SWZ((u32)((tid >> 2) * 64 + (tid & 3) * 16));

    const u32 lswz = ((((u32)lane & 15u) >> 1) & 3u) << 4;
    const u32 aRow = uSA + (u32)(wr * 64 + (lane & 15)) * 64;
    const u32 bRow = uSB + (u32)(wc * 32 + (lane & 15)) * 64;
    const u32 chnk = ((u32)lane >> 4) * 16;

    float c[4][4][4];
    #pragma unroll
    for (int i = 0; i < 4; i++)
        #pragma unroll
        for (int j = 0; j < 4; j++)
            #pragma unroll
            for (int k = 0; k < 4; k++) c[i][j][k] = 0.f;

    #pragma unroll
    for (int p = 0; p < 3; p++) {
        cp16(aDst0 + p * 16384, aSrc0 + p * 32);
        cp16(aDst1 + p * 16384, aSrc1 + p * 32);
        cp16(bDst  + p * 8192,  bSrc  + p * 32);
        asm volatile("cp.async.commit_group;" ::: "memory");
    }

    for (int s = 0; s < NST; s++) {
        if (s < NST - 2)       asm volatile("cp.async.wait_group 2;" ::: "memory");
        else if (s == NST - 2) asm volatile("cp.async.wait_group 1;" ::: "memory");
        else                   asm volatile("cp.async.wait_group 0;" ::: "memory");
        __syncthreads();

        if (s + 3 < NST) {
            const int p = s + 3, pb = p & 3;
            cp16(aDst0 + pb * 16384, aSrc0 + p * 32);
            cp16(aDst1 + pb * 16384, aSrc1 + p * 32);
            cp16(bDst  + pb * 8192,  bSrc  + p * 32);
            asm volatile("cp.async.commit_group;" ::: "memory");
        }

        const u32 bufA = (u32)(s & 3) * 16384, bufB = (u32)(s & 3) * 8192;
        #pragma unroll
        for (int kh = 0; kh < 2; kh++) {
            const u32 cx = (chnk + kh * 32) ^ lswz;
            u32 a[4][4], b[2][4];
            #pragma unroll
            for (int mf = 0; mf < 4; mf++)
                ldsm4(a[mf], aRow + bufA + mf * 1024 + cx);
            #pragma unroll
            for (int nb2 = 0; nb2 < 2; nb2++)
                ldsm4(b[nb2], bRow + bufB + nb2 * 1024 + cx);
            #pragma unroll
            for (int mf = 0; mf < 4; mf++)
                #pragma unroll
                for (int nf = 0; nf < 4; nf++)
                    mma16816(c[mf][nf], a[mf], b[nf >> 1][nf & 1], b[nf >> 1][(nf & 1) + 2]);
        }
    }
    __syncthreads();

    // ---- epilogue: per-row min over this 128-code tile ----
    u64* sp1 = (u64*)smem_raw;                     // [256][4]

    float cn[4][2];
    #pragma unroll
    for (int nf = 0; nf < 4; nf++)
        #pragma unroll
        for (int j = 0; j < 2; j++)
            cn[nf][j] = __ldg(&g_cnorm[ntb * 128 + wc * 32 + nf * 8 + (lane & 3) * 2 + j]);

    #pragma unroll
    for (int mf = 0; mf < 4; mf++) {
        #pragma unroll
        for (int h = 0; h < 2; h++) {
            u64 p1 = P1INIT;
            #pragma unroll
            for (int nf = 0; nf < 4; nf++) {
                #pragma unroll
                for (int j = 0; j < 2; j++) {
                    float sc = fmaf(-2.f, c[mf][nf][h * 2 + j], cn[nf][j]);
                    int k = ntb * 128 + wc * 32 + nf * 8 + (lane & 3) * 2 + j;
                    u64 p = ((u64)ford(sc) << 32) | (u32)k;
                    if (p < p1) p1 = p;
                }
            }
            #pragma unroll
            for (int off = 1; off <= 2; off <<= 1) {
                u64 po = __shfl_xor_sync(0xFFFFFFFFu, p1, off);
                if (po < p1) p1 = po;
            }
            if ((lane & 3) == 0) {
                int row = wr * 64 + mf * 16 + (lane >> 2) + h * 8;
                sp1[row * 4 + wc] = p1;
            }
        }
    }
    __syncthreads();
    if (tid < 256) {
        u64 p1 = sp1[tid * 4];
        #pragma unroll
        for (int w = 1; w < 4; w++) {
            u64 po = sp1[tid * 4 + w];
            if (po < p1) p1 = po;
        }
        g_m1[(size_t)ntb * NVEC + rt * 256 + tid] = p1;
    }
}

// ---------------- per-row approx min + per-row candidate threshold ----------------
__global__ void k_reduce() {
    int row = blockIdx.x * 256 + threadIdx.x;
    u64 p1 = 0xFFFFFFFFFFFFFFFFull;
    for (int nt = 0; nt < NTILES; nt++) {
        u64 q = g_m1[(size_t)nt * NVEC + row];
        if (q < p1) p1 = q;
    }
    g_rowmin[row] = funord((u32)(p1 >> 32));
    // TH = 4*(n1z*n2c + n2z*n1c + n2z*n2c) + slack  (2x per-tile err, two tiles)
    float n1c = __uint_as_float(g_n1c), n2c = __uint_as_float(g_n2c);
    float n1z = g_zn1[row], n2z = g_zn2[row];
    g_rowth[row] = 4.f * (n1z * n2c + n2z * n1c + n2z * n2c) + 0.05f;
    g_best[row] = 0xFFFFFFFFFFFFFFFFull;
}

// ---------------- exact fp32 rescan of candidate (row, tile) pairs ----------------
__global__ __launch_bounds__(256) void k_rescue(const float* __restrict__ z, const float* __restrict__ cb) {
    __shared__ float zrow[D_];
    __shared__ int list[128];
    __shared__ int cnt;
    const int tid = threadIdx.x, wid = tid >> 5, lane = tid & 31;
    const int rt = blockIdx.x, ct = blockIdx.y;    // 64 row tiles x 64 code tiles

    if (tid == 0) cnt = 0;
    __syncthreads();

    if (tid < 128) {
        int row = rt * 128 + tid;
        float sc = funord((u32)(g_m1[(size_t)ct * NVEC + row] >> 32));
        if (sc <= g_rowmin[row] + g_rowth[row]) { int p = atomicAdd(&cnt, 1); list[p] = row; }
    }
    __syncthreads();
    const int nv = cnt;
    if (!nv) return;

    for (int e = 0; e < nv; e++) {
        const int row = list[e], b = row >> 8, t = row & 255;
        for (int d = tid; d < D_; d += 256)
            zrow[d] = z[(size_t)b * D_ * T_ + (size_t)d * T_ + t];
        __syncthreads();
        u64 loc = 0xFFFFFFFFFFFFFFFFull;
        #pragma unroll 1
        for (int i = 0; i < 16; i++) {
            const int code = ct * 128 + wid * 16 + i;
            const float* crow = cb + (size_t)code * D_;
            float dot = 0.f;
            #pragma unroll
            for (int j = 0; j < 16; j++)
                dot = fmaf(crow[lane + j * 32], zrow[lane + j * 32], dot);
            #pragma unroll
            for (int o = 16; o; o >>= 1) dot += __shfl_xor_sync(0xFFFFFFFFu, dot, o);
            if (!lane) {
                float sc = fmaf(-2.f, dot, g_cnorm[code]);
                u64 p = ((u64)ford(sc) << 32) | (u32)code;
                if (p < loc) loc = p;
            }
        }
        if (!lane) atomicMin(&g_best[row], loc);
        __syncthreads();
    }
}

// ---------------- gather + transpose + loss + counts (fused) ----------------
__global__ void k_gather(const float* __restrict__ z, const float* __restrict__ cb, float* __restrict__ out) {
    __shared__ float red[256];
    int n = blockIdx.x * 256 + threadIdx.x;
    int b = n >> 8, t = n & 255;
    int dlo = blockIdx.y * 128;
    int idx = (int)(g_best[n] & 0xFFFFFFFFull);
    if (blockIdx.y == 0) atomicAdd(&g_counts[idx], 1);
    const float* crow = cb + (size_t)idx * D_ + dlo;
    const float* zb = z + (size_t)b * D_ * T_ + (size_t)dlo * T_ + t;
    float* ob = out + (size_t)b * D_ * T_ + (size_t)dlo * T_ + t;
    float s = 0.f;
    #pragma unroll 8
    for (int d = 0; d < 128; d++) {
        float cv = __ldg(crow + d);
        float zv = zb[d * T_];
        ob[d * T_] = cv;
        float df = cv - zv;
        s = fmaf(df, df, s);
    }
    red[threadIdx.x] = s;
    __syncthreads();
    for (int st = 128; st; st >>= 1) {
        if (threadIdx.x < st) red[threadIdx.x] += red[threadIdx.x + st];
        __syncthreads();
    }
    if (!threadIdx.x) atomicAdd(&g_loss, red[0]);
}

// ---------------- scalars ----------------
__global__ void k_final(float* __restrict__ out, int out_size) {
    __shared__ float red[256];
    float s = 0.f;
    for (int k = threadIdx.x; k < KCODE; k += 256) {
        float p = (float)g_counts[k] / (float)NVEC;
        s += p * logf(p + 1e-10f);
    }
    red[threadIdx.x] = s;
    __syncthreads();
    for (int st = 128; st; st >>= 1) {
        if (threadIdx.x < st) red[threadIdx.x] += red[threadIdx.x + st];
        __syncthreads();
    }
    if (!threadIdx.x) {
        out[out_size - 2] = 0.25f * g_loss / (float)((size_t)NVEC * D_);
        out[out_size - 1] = expf(-red[0]);
    }
}

extern "C" void kernel_launch(void* const* d_in, const int* in_sizes, int n_in,
                              void* d_out, int out_size) {
    const float* z  = (const float*)d_in[0];   // (B, D, T) fp32
    const float* cb = (const float*)d_in[1];   // (K, D) fp32
    float* out = (float*)d_out;

    cudaFuncSetAttribute(k_gemm, cudaFuncAttributeMaxDynamicSharedMemorySize, 98304);

    k_init<<<32, 256>>>();
    k_prep_z<<<32, 256>>>(z);
    k_prep_cb<<<1024, 256>>>(cb);
    k_gemm<<<dim3(32, 64), 512, 98304>>>();
    k_reduce<<<32, 256>>>();
    k_rescue<<<dim3(64, 64), 256>>>(z, cb);
    k_gather<<<dim3(32, 4), 256>>>(z, cb, out);
    k_final<<<1, 256>>>(out, out_size);
}

// round 9
// speedup vs baseline: 4.3276x; 1.0108x over previous
#include <cuda_runtime.h>
#include <cuda_fp16.h>
#include <math.h>
#include <stdint.h>

#define B_    32
#define T_    256
#define D_    512
#define NVEC  8192     // B_*T_
#define KCODE 8192
#define KS    512      // single fp16 slot per dim
#define NTILES 64      // 64 code tiles of 128
#define NST   16       // K stages of 32

typedef unsigned long long u64;
typedef unsigned int u32;

// ---------------- device scratch ----------------
__device__ __align__(16) __half g_A[(size_t)NVEC * KS];    // 8MB fp16 z
__device__ __align__(16) __half g_Bm[(size_t)KCODE * KS];  // 8MB fp16 codebook
__device__ u64   g_m1[(size_t)NTILES * NVEC];              // per-tile packed min (approx)
__device__ float g_rowmin[NVEC];                           // per-row approx min score
__device__ float g_rowth[NVEC];                            // per-row candidate threshold
__device__ u64   g_best[NVEC];
__device__ float g_cnorm[KCODE];
__device__ float g_zn1[NVEC], g_zn2[NVEC];                 // per-row ||z1||, ||z_res||
__device__ int   g_counts[KCODE];
__device__ float g_loss;
__device__ u32 g_n1c, g_n2c;                               // global max ||c1||, ||c_res||

// ---------------- ordered float packing ----------------
__device__ __forceinline__ u32 ford(float f) {
    u32 u = __float_as_uint(f);
    return u ^ ((u >> 31) ? 0xFFFFFFFFu : 0x80000000u);
}
__device__ __forceinline__ float funord(u32 u) {
    u ^= ((u >> 31) ? 0x80000000u : 0xFFFFFFFFu);
    return __uint_as_float(u);
}
#define P1INIT 0xFF800000FFFFFFFFull

__device__ __forceinline__ u32 smem_u32(const void* p) {
    u32 a;
    asm("{ .reg .u64 t; cvta.to.shared.u64 t, %1; cvt.u32.u64 %0, t; }" : "=r"(a) : "l"(p));
    return a;
}
__device__ __forceinline__ void cp16(u32 dst, const void* src) {
    asm volatile("cp.async.cg.shared.global [%0], [%1], 16;" :: "r"(dst), "l"(src) : "memory");
}
__device__ __forceinline__ void ldsm4(u32* r, u32 addr) {
    asm volatile("ldmatrix.sync.aligned.m8n8.x4.shared.b16 {%0,%1,%2,%3}, [%4];"
        : "=r"(r[0]), "=r"(r[1]), "=r"(r[2]), "=r"(r[3]) : "r"(addr));
}
__device__ __forceinline__ void mma16816(float* c, const u32* a, u32 b0, u32 b1) {
    asm volatile("mma.sync.aligned.m16n8k16.row.col.f32.f16.f16.f32 "
        "{%0,%1,%2,%3}, {%4,%5,%6,%7}, {%8,%9}, {%0,%1,%2,%3};"
        : "+f"(c[0]), "+f"(c[1]), "+f"(c[2]), "+f"(c[3])
        : "r"(a[0]), "r"(a[1]), "r"(a[2]), "r"(a[3]), "r"(b0), "r"(b1));
}
#define SWZ(o) ((o) ^ (((o) >> 3) & 0x30))

// ---------------- reset ----------------
__global__ void k_init() {
    int i = blockIdx.x * 256 + threadIdx.x;
    if (i < KCODE) g_counts[i] = 0;
    if (i == 0) { g_loss = 0.f; g_n1c = 0u; g_n2c = 0u; }
}

// ---------------- z -> fp16 + per-row residual norms ----------------
__global__ void k_prep_z(const float* __restrict__ z) {
    int n = blockIdx.x * 256 + threadIdx.x;
    int b = n >> 8, t = n & 255;
    const float* zb = z + (size_t)b * D_ * T_ + t;
    __half* arow = g_A + (size_t)n * KS;
    float n1 = 0.f, n2 = 0.f;
    for (int d0 = 0; d0 < D_; d0 += 8) {
        union { unsigned short u[8]; uint4 q; } w;
        #pragma unroll
        for (int j = 0; j < 8; j++) {
            float v = zb[(d0 + j) * T_];
            __half h1 = __float2half_rn(v);
            float f1 = __half2float(h1);
            float r = v - f1;
            n1 = fmaf(f1, f1, n1);
            n2 = fmaf(r, r, n2);
            w.u[j] = __half_as_ushort(h1);
        }
        *(uint4*)(arow + d0) = w.q;
    }
    g_zn1[n] = sqrtf(n1);
    g_zn2[n] = sqrtf(n2);
}

// ---------------- codebook -> fp16 + cnorm + global residual norm maxes ----------------
__global__ void k_prep_cb(const float* __restrict__ cb) {
    int code = (blockIdx.x * 256 + threadIdx.x) >> 5;
    int lane = threadIdx.x & 31;
    if (code >= KCODE) return;
    const float* row = cb + (size_t)code * D_;
    __half* brow = g_Bm + (size_t)code * KS;
    float n1 = 0.f, n2 = 0.f, N2 = 0.f;
    #pragma unroll
    for (int pass = 0; pass < 2; pass++) {
        int d0 = pass * 256 + lane * 8;
        float4 va = *(const float4*)(row + d0);
        float4 vb = *(const float4*)(row + d0 + 4);
        float vv[8] = { va.x, va.y, va.z, va.w, vb.x, vb.y, vb.z, vb.w };
        union { unsigned short u[8]; uint4 q; } w;
        #pragma unroll
        for (int j = 0; j < 8; j++) {
            float v = vv[j];
            N2 = fmaf(v, v, N2);
            __half h1 = __float2half_rn(v);
            float f1 = __half2float(h1);
            float r = v - f1;
            n1 = fmaf(f1, f1, n1);
            n2 = fmaf(r, r, n2);
            w.u[j] = __half_as_ushort(h1);
        }
        *(uint4*)(brow + d0) = w.q;
    }
    #pragma unroll
    for (int o = 16; o; o >>= 1) {
        N2 += __shfl_xor_sync(0xFFFFFFFFu, N2, o);
        n1 += __shfl_xor_sync(0xFFFFFFFFu, n1, o);
        n2 += __shfl_xor_sync(0xFFFFFFFFu, n2, o);
    }
    if (!lane) {
        g_cnorm[code] = N2;
        atomicMax(&g_n1c, __float_as_uint(sqrtf(n1)));
        atomicMax(&g_n2c, __float_as_uint(sqrtf(n2)));
    }
}

// ---------------- fp16 mma.sync GEMM (128x128 CTA tile, 2 CTAs/SM, K=512, 4-stage) ----------------
__global__ __launch_bounds__(256, 2)
void k_gemm() {
    extern __shared__ __align__(128) char smem_raw[];   // A: 4x8KB | B: 4x8KB = 64KB
    const int tid = threadIdx.x;
    const int wid = tid >> 5, lane = tid & 31;
    const int wr = wid >> 2, wc = wid & 3;            // 2x4 warp grid, warp tile 64x32
    const int rt = blockIdx.x;                        // 128 z-rows
    const int ntb = blockIdx.y;                       // 128 codes
    const u32 uSA = smem_u32(smem_raw);
    const u32 uSB = uSA + 32768;

    const __half* Abase = g_A  + (size_t)rt  * 128 * KS;
    const __half* Bbase = g_Bm + (size_t)ntb * 128 * KS;

    // cp.async: 256 threads, rows tid>>2 and tid>>2 + 64, 4 chunks of 16B each
    const __half* aSrc0 = Abase + (size_t)(tid >> 2) * KS + (tid & 3) * 8;
    const __half* aSrc1 = aSrc0 + (size_t)64 * KS;
    const __half* bSrc0 = Bbase + (size_t)(tid >> 2) * KS + (tid & 3) * 8;
    const __half* bSrc1 = bSrc0 + (size_t)64 * KS;
    const u32 aDst0 = uSA + SWZ((u32)((tid >> 2) * 64 + (tid & 3) * 16));
    const u32 aDst1 = uSA + SWZ((u32)(((tid >> 2) + 64) * 64 + (tid & 3) * 16));
    const u32 bDst0 = uSB + SWZ((u32)((tid >> 2) * 64 + (tid & 3) * 16));
    const u32 bDst1 = uSB + SWZ((u32)(((tid >> 2) + 64) * 64 + (tid & 3) * 16));

    const u32 lswz = ((((u32)lane & 15u) >> 1) & 3u) << 4;
    const u32 aRow = uSA + (u32)(wr * 64 + (lane & 15)) * 64;
    const u32 bRow = uSB + (u32)(wc * 32 + (lane & 15)) * 64;
    const u32 chnk = ((u32)lane >> 4) * 16;

    float c[4][4][4];
    #pragma unroll
    for (int i = 0; i < 4; i++)
        #pragma unroll
        for (int j = 0; j < 4; j++)
            #pragma unroll
            for (int k = 0; k < 4; k++) c[i][j][k] = 0.f;

    #pragma unroll
    for (int p = 0; p < 3; p++) {
        cp16(aDst0 + p * 8192, aSrc0 + p * 32);
        cp16(aDst1 + p * 8192, aSrc1 + p * 32);
        cp16(bDst0 + p * 8192, bSrc0 + p * 32);
        cp16(bDst1 + p * 8192, bSrc1 + p * 32);
        asm volatile("cp.async.commit_group;" ::: "memory");
    }

    for (int s = 0; s < NST; s++) {
        if (s < NST - 2)       asm volatile("cp.async.wait_group 2;" ::: "memory");
        else if (s == NST - 2) asm volatile("cp.async.wait_group 1;" ::: "memory");
        else                   asm volatile("cp.async.wait_group 0;" ::: "memory");
        __syncthreads();

        if (s + 3 < NST) {
            const int p = s + 3, pb = p & 3;
            cp16(aDst0 + pb * 8192, aSrc0 + p * 32);
            cp16(aDst1 + pb * 8192, aSrc1 + p * 32);
            cp16(bDst0 + pb * 8192, bSrc0 + p * 32);
            cp16(bDst1 + pb * 8192, bSrc1 + p * 32);
            asm volatile("cp.async.commit_group;" ::: "memory");
        }

        const u32 buf = (u32)(s & 3) * 8192;
        #pragma unroll
        for (int kh = 0; kh < 2; kh++) {
            const u32 cx = (chnk + kh * 32) ^ lswz;
            u32 a[4][4], b[2][4];
            #pragma unroll
            for (int mf = 0; mf < 4; mf++)
                ldsm4(a[mf], aRow + buf + mf * 1024 + cx);
            #pragma unroll
            for (int nb2 = 0; nb2 < 2; nb2++)
                ldsm4(b[nb2], bRow + buf + nb2 * 1024 + cx);
            #pragma unroll
            for (int mf = 0; mf < 4; mf++)
                #pragma unroll
                for (int nf = 0; nf < 4; nf++)
                    mma16816(c[mf][nf], a[mf], b[nf >> 1][nf & 1], b[nf >> 1][(nf & 1) + 2]);
        }
    }
    __syncthreads();

    // ---- epilogue: per-row min over this 128-code tile ----
    u64* sp1 = (u64*)smem_raw;                     // [128][4]

    float cn[4][2];
    #pragma unroll
    for (int nf = 0; nf < 4; nf++)
        #pragma unroll
        for (int j = 0; j < 2; j++)
            cn[nf][j] = __ldg(&g_cnorm[ntb * 128 + wc * 32 + nf * 8 + (lane & 3) * 2 + j]);

    #pragma unroll
    for (int mf = 0; mf < 4; mf++) {
        #pragma unroll
        for (int h = 0; h < 2; h++) {
            u64 p1 = P1INIT;
            #pragma unroll
            for (int nf = 0; nf < 4; nf++) {
                #pragma unroll
                for (int j = 0; j < 2; j++) {
                    float sc = fmaf(-2.f, c[mf][nf][h * 2 + j], cn[nf][j]);
                    int k = ntb * 128 + wc * 32 + nf * 8 + (lane & 3) * 2 + j;
                    u64 p = ((u64)ford(sc) << 32) | (u32)k;
                    if (p < p1) p1 = p;
                }
            }
            #pragma unroll
            for (int off = 1; off <= 2; off <<= 1) {
                u64 po = __shfl_xor_sync(0xFFFFFFFFu, p1, off);
                if (po < p1) p1 = po;
            }
            if ((lane & 3) == 0) {
                int row = wr * 64 + mf * 16 + (lane >> 2) + h * 8;
                sp1[row * 4 + wc] = p1;
            }
        }
    }
    __syncthreads();
    if (tid < 128) {
        u64 p1 = sp1[tid * 4];
        #pragma unroll
        for (int w = 1; w < 4; w++) {
            u64 po = sp1[tid * 4 + w];
            if (po < p1) p1 = po;
        }
        g_m1[(size_t)ntb * NVEC + rt * 128 + tid] = p1;
    }
}

// ---------------- per-row approx min + per-row candidate threshold ----------------
__global__ void k_reduce() {
    int row = blockIdx.x * 256 + threadIdx.x;
    u64 p1 = 0xFFFFFFFFFFFFFFFFull;
    for (int nt = 0; nt < NTILES; nt++) {
        u64 q = g_m1[(size_t)nt * NVEC + row];
        if (q < p1) p1 = q;
    }
    g_rowmin[row] = funord((u32)(p1 >> 32));
    float n1c = __uint_as_float(g_n1c), n2c = __uint_as_float(g_n2c);
    float n1z = g_zn1[row], n2z = g_zn2[row];
    g_rowth[row] = 4.f * (n1z * n2c + n2z * n1c + n2z * n2c) + 0.05f;
    g_best[row] = 0xFFFFFFFFFFFFFFFFull;
}

// ---------------- exact fp32 rescan of candidate (row, tile) pairs ----------------
__global__ __launch_bounds__(256) void k_rescue(const float* __restrict__ z, const float* __restrict__ cb) {
    __shared__ float zrow[D_];
    __shared__ int list[128];
    __shared__ int cnt;
    const int tid = threadIdx.x, wid = tid >> 5, lane = tid & 31;
    const int rt = blockIdx.x, ct = blockIdx.y;    // 64 row tiles x 64 code tiles

    if (tid == 0) cnt = 0;
    __syncthreads();

    if (tid < 128) {
        int row = rt * 128 + tid;
        float sc = funord((u32)(g_m1[(size_t)ct * NVEC + row] >> 32));
        if (sc <= g_rowmin[row] + g_rowth[row]) { int p = atomicAdd(&cnt, 1); list[p] = row; }
    }
    __syncthreads();
    const int nv = cnt;
    if (!nv) return;

    for (int e = 0; e < nv; e++) {
        const int row = list[e], b = row >> 8, t = row & 255;
        for (int d = tid; d < D_; d += 256)
            zrow[d] = z[(size_t)b * D_ * T_ + (size_t)d * T_ + t];
        __syncthreads();
        u64 loc = 0xFFFFFFFFFFFFFFFFull;
        #pragma unroll 1
        for (int i = 0; i < 16; i++) {
            const int code = ct * 128 + wid * 16 + i;
            const float* crow = cb + (size_t)code * D_;
            float dot = 0.f;
            #pragma unroll
            for (int j = 0; j < 16; j++)
                dot = fmaf(crow[lane + j * 32], zrow[lane + j * 32], dot);
            #pragma unroll
            for (int o = 16; o; o >>= 1) dot += __shfl_xor_sync(0xFFFFFFFFu, dot, o);
            if (!lane) {
                float sc = fmaf(-2.f, dot, g_cnorm[code]);
                u64 p = ((u64)ford(sc) << 32) | (u32)code;
                if (p < loc) loc = p;
            }
        }
        if (!lane) atomicMin(&g_best[row], loc);
        __syncthreads();
    }
}

// ---------------- gather + transpose + loss + counts (fused) ----------------
__global__ void k_gather(const float* __restrict__ z, const float* __restrict__ cb, float* __restrict__ out) {
    __shared__ float red[256];
    int n = blockIdx.x * 256 + threadIdx.x;
    int b = n >> 8, t = n & 255;
    int dlo = blockIdx.y * 128;
    int idx = (int)(g_best[n] & 0xFFFFFFFFull);
    if (blockIdx.y == 0) atomicAdd(&g_counts[idx], 1);
    const float* crow = cb + (size_t)idx * D_ + dlo;
    const float* zb = z + (size_t)b * D_ * T_ + (size_t)dlo * T_ + t;
    float* ob = out + (size_t)b * D_ * T_ + (size_t)dlo * T_ + t;
    float s = 0.f;
    #pragma unroll 8
    for (int d = 0; d < 128; d++) {
        float cv = __ldg(crow + d);
        float zv = zb[d * T_];
        ob[d * T_] = cv;
        float df = cv - zv;
        s = fmaf(df, df, s);
    }
    red[threadIdx.x] = s;
    __syncthreads();
    for (int st = 128; st; st >>= 1) {
        if (threadIdx.x < st) red[threadIdx.x] += red[threadIdx.x + st];
        __syncthreads();
    }
    if (!threadIdx.x) atomicAdd(&g_loss, red[0]);
}

// ---------------- scalars ----------------
__global__ void k_final(float* __restrict__ out, int out_size) {
    __shared__ float red[256];
    float s = 0.f;
    for (int k = threadIdx.x; k < KCODE; k += 256) {
        float p = (float)g_counts[k] / (float)NVEC;
        s += p * logf(p + 1e-10f);
    }
    red[threadIdx.x] = s;
    __syncthreads();
    for (int st = 128; st; st >>= 1) {
        if (threadIdx.x < st) red[threadIdx.x] += red[threadIdx.x + st];
        __syncthreads();
    }
    if (!threadIdx.x) {
        out[out_size - 2] = 0.25f * g_loss / (float)((size_t)NVEC * D_);
        out[out_size - 1] = expf(-red[0]);
    }
}

extern "C" void kernel_launch(void* const* d_in, const int* in_sizes, int n_in,
                              void* d_out, int out_size) {
    const float* z  = (const float*)d_in[0];   // (B, D, T) fp32
    const float* cb = (const float*)d_in[1];   // (K, D) fp32
    float* out = (float*)d_out;

    cudaFuncSetAttribute(k_gemm, cudaFuncAttributeMaxDynamicSharedMemorySize, 65536);

    k_init<<<32, 256>>>();
    k_prep_z<<<32, 256>>>(z);
    k_prep_cb<<<1024, 256>>>(cb);
    k_gemm<<<dim3(64, 64), 256, 65536>>>();
    k_reduce<<<32, 256>>>();
    k_rescue<<<dim3(64, 64), 256>>>(z, cb);
    k_gather<<<dim3(32, 4), 256>>>(z, cb, out);
    k_final<<<1, 256>>>(out, out_size);
}